// round 11
// baseline (speedup 1.0000x reference)
#include <cuda_runtime.h>
#include <cuda_fp16.h>
#include <math.h>
#include <stdint.h>

// ---------------- problem constants ----------------
#define BB   2
#define SS   2048
#define DD   2048
#define HH   16
#define HHK  8
#define HD   128
#define MM   (BB*SS)          // 4096 tokens

// ---------------- scratch (device globals) ----------------
__device__ __align__(256) float  g_q[MM * HH * HD];
__device__ __align__(256) float  g_k[MM * HHK * HD];
__device__ __align__(256) __half g_xh[MM * DD],     g_xl[MM * DD];
__device__ __align__(256) __half g_wqkv[(HH + 2 * HHK) * HD * DD];
__device__ __align__(256) __half g_woh[DD * HH * HD];
__device__ __align__(256) __half g_qh[MM*HH*HD],    g_ql[MM*HH*HD];
__device__ __align__(256) __half g_kh[MM*HHK*HD],   g_kl[MM*HHK*HD];
__device__ __align__(256) __half g_vh[MM*HHK*HD],   g_vl[MM*HHK*HD];
__device__ __align__(256) __half g_ah[MM*HH*HD],    g_al[MM*HH*HD];
__device__ __align__(256) float  g_ct[SS * 64],     g_st[SS * 64];

// ============================================================
// helpers
// ============================================================
__device__ __forceinline__ uint32_t smem_u32(const void* p) {
    uint32_t a;
    asm("{ .reg .u64 t; cvta.to.shared.u64 t, %1; cvt.u32.u64 %0, t; }"
        : "=r"(a) : "l"(p));
    return a;
}
__device__ __forceinline__ void ldsm4(uint32_t* r, uint32_t addr) {
    asm volatile("ldmatrix.sync.aligned.m8n8.x4.shared.b16 {%0,%1,%2,%3}, [%4];"
                 : "=r"(r[0]), "=r"(r[1]), "=r"(r[2]), "=r"(r[3]) : "r"(addr));
}
__device__ __forceinline__ void ldsm4t(uint32_t* r, uint32_t addr) {
    asm volatile("ldmatrix.sync.aligned.m8n8.x4.trans.shared.b16 {%0,%1,%2,%3}, [%4];"
                 : "=r"(r[0]), "=r"(r[1]), "=r"(r[2]), "=r"(r[3]) : "r"(addr));
}
__device__ __forceinline__ void mma16816(float* c, const uint32_t* a,
                                         uint32_t b0, uint32_t b1) {
    asm volatile(
        "mma.sync.aligned.m16n8k16.row.col.f32.f16.f16.f32 "
        "{%0,%1,%2,%3}, {%4,%5,%6,%7}, {%8,%9}, {%0,%1,%2,%3};"
        : "+f"(c[0]), "+f"(c[1]), "+f"(c[2]), "+f"(c[3])
        : "r"(a[0]), "r"(a[1]), "r"(a[2]), "r"(a[3]), "r"(b0), "r"(b1));
}
#define CP16(dst, src) asm volatile("cp.async.cg.shared.global [%0], [%1], 16;" \
                                    :: "r"(dst), "l"(src))
#define CP_COMMIT()    asm volatile("cp.async.commit_group;" ::: "memory")
#define CP_WAIT0()     asm volatile("cp.async.wait_group 0;" ::: "memory")
#define CP_WAIT1()     asm volatile("cp.async.wait_group 1;" ::: "memory")

// ============================================================
// small prep kernels
// ============================================================
__global__ void split_fp16(const float* __restrict__ src, __half* __restrict__ hi,
                           __half* __restrict__ lo, int n4) {
    int i = blockIdx.x * blockDim.x + threadIdx.x;
    if (i >= n4) return;
    float4 v = ((const float4*)src)[i];
    __half2 h01 = __floats2half2_rn(v.x, v.y);
    __half2 h23 = __floats2half2_rn(v.z, v.w);
    float2 f01 = __half22float2(h01), f23 = __half22float2(h23);
    __half2 l01 = __floats2half2_rn(v.x - f01.x, v.y - f01.y);
    __half2 l23 = __floats2half2_rn(v.z - f23.x, v.w - f23.y);
    ((__half2*)hi)[2*i] = h01; ((__half2*)hi)[2*i+1] = h23;
    ((__half2*)lo)[2*i] = l01; ((__half2*)lo)[2*i+1] = l23;
}

#define W_Q4 (HH*HD*DD/4)
#define W_K4 (HHK*HD*DD/4)
#define W_O4 (DD*HH*HD/4)
__global__ void cast_all(const float* __restrict__ wq, const float* __restrict__ wk,
                         const float* __restrict__ wv, const float* __restrict__ wo,
                         __half* __restrict__ wqkv, __half* __restrict__ woh) {
    int i = blockIdx.x * blockDim.x + threadIdx.x;
    const float* src; __half* dst; int j;
    if (i < W_Q4)                { src = wq; dst = wqkv;                     j = i; }
    else if (i < W_Q4 + W_K4)    { src = wk; dst = wqkv + HH*HD*DD;          j = i - W_Q4; }
    else if (i < W_Q4 + 2*W_K4)  { src = wv; dst = wqkv + (HH+HHK)*HD*DD;    j = i - W_Q4 - W_K4; }
    else                         { src = wo; dst = woh;                      j = i - W_Q4 - 2*W_K4; }
    float4 v = ((const float4*)src)[j];
    ((__half2*)dst)[2*j]   = __floats2half2_rn(v.x, v.y);
    ((__half2*)dst)[2*j+1] = __floats2half2_rn(v.z, v.w);
}

__global__ void rope_table(float* __restrict__ ct, float* __restrict__ st) {
    int idx = blockIdx.x * blockDim.x + threadIdx.x;   // SS*64
    int s = idx >> 6, i = idx & 63;
    float inv_freq = powf(1.0e6f, -(float)i * (1.0f / 64.0f));
    float sn, cs;
    sincosf((float)s * inv_freq, &sn, &cs);
    ct[idx] = cs; st[idx] = sn;
}

// ============================================================
// HMMA fp16x2-split GEMM: C = A*W^T, A split hi/lo, W fp16.
// CTA 128x128, BK=32, **128 threads, 4 warps, warp tile 64x64**.
// 3-stage cp.async (72KB).  epi 0: fp32; epi 2: fused QKV epilogue.
// ============================================================
#define GEMM_SMEM (3 * 24576)

__global__ __launch_bounds__(128)
void gemm_h(const __half* __restrict__ Ah, const __half* __restrict__ Al,
            const __half* __restrict__ Bh,
            float* __restrict__ Cf, float* __restrict__ Kf,
            __half* __restrict__ Ch, __half* __restrict__ Cl,
            int M, int N, int K, int epi) {
    extern __shared__ char smc[];
    const uint32_t sb = smem_u32(smc);
    const int tid  = threadIdx.x;
    const int lane = tid & 31;
    const int wid  = tid >> 5;          // 0..3
    const int wm   = wid & 1;           // 2 warps over M (64 rows)
    const int wn   = wid >> 1;          // 2 warps over N (64 cols)
    const int brow = blockIdx.y * 128;
    const int bcol = blockIdx.x * 128;

    const __half* Agh = Ah + (size_t)brow * K;
    const __half* Agl = Al + (size_t)brow * K;
    const __half* Bgh = Bh + (size_t)bcol * K;

    const int lr = tid >> 2;            // 0..31
    const int kq = tid & 3;

    auto issue = [&](int stage, int k0) {
        const uint32_t stb = sb + stage * 24576;
        #pragma unroll
        for (int i = 0; i < 4; ++i) {
            int r = lr + i * 32;
            uint32_t so = (uint32_t)(r * 64 + ((kq ^ ((r >> 1) & 3)) * 16));
            size_t go = (size_t)r * K + k0 + kq * 8;
            CP16(stb + so,         Agh + go);
            CP16(stb + 8192 + so,  Agl + go);
            CP16(stb + 16384 + so, Bgh + go);
        }
    };

    float acc[4][8][4];
    #pragma unroll
    for (int mt = 0; mt < 4; ++mt)
        #pragma unroll
        for (int nt = 0; nt < 8; ++nt)
            #pragma unroll
            for (int e = 0; e < 4; ++e) acc[mt][nt][e] = 0.f;

    const int nk = K >> 5;
    issue(0, 0);  CP_COMMIT();
    issue(1, 32); CP_COMMIT();

    const int lrow16 = lane & 15;
    const int lhalf  = lane >> 4;

    for (int c = 0; c < nk; ++c) {
        CP_WAIT1();
        __syncthreads();
        const uint32_t stb = sb + (c % 3) * 24576;

        #pragma unroll
        for (int ks = 0; ks < 2; ++ks) {
            uint32_t ah[4][4], al[4][4], bh[4][4];
            #pragma unroll
            for (int mt = 0; mt < 4; ++mt) {
                int row = wm * 64 + mt * 16 + lrow16;
                int atom = (ks * 2 + lhalf) ^ ((row >> 1) & 3);
                uint32_t ad = stb + (uint32_t)(row * 64 + atom * 16);
                ldsm4(ah[mt], ad);
                ldsm4(al[mt], ad + 8192);
            }
            #pragma unroll
            for (int g2 = 0; g2 < 4; ++g2) {
                int row = wn * 64 + g2 * 16 + lrow16;
                int atom = (ks * 2 + lhalf) ^ ((row >> 1) & 3);
                uint32_t ad = stb + 16384 + (uint32_t)(row * 64 + atom * 16);
                ldsm4(bh[g2], ad);
            }
            #pragma unroll
            for (int mt = 0; mt < 4; ++mt)
                #pragma unroll
                for (int nt = 0; nt < 8; ++nt) {
                    const int g2 = nt >> 1, s2 = nt & 1;
                    mma16816(acc[mt][nt], ah[mt], bh[g2][s2], bh[g2][s2 + 2]);
                    mma16816(acc[mt][nt], al[mt], bh[g2][s2], bh[g2][s2 + 2]);
                }
        }
        if (c + 2 < nk) issue((c + 2) % 3, (c + 2) << 5);
        CP_COMMIT();
    }

    // ---- epilogue ----
    #pragma unroll
    for (int mt = 0; mt < 4; ++mt) {
        int row = brow + wm * 64 + mt * 16 + (lane >> 2);
        #pragma unroll
        for (int nt = 0; nt < 8; ++nt) {
            int col = bcol + wn * 64 + nt * 8 + (lane & 3) * 2;
            if (epi == 0) {
                float* p0 = Cf + (size_t)row * N + col;
                *(float2*)p0 = make_float2(acc[mt][nt][0], acc[mt][nt][1]);
                *(float2*)(p0 + (size_t)8 * N) = make_float2(acc[mt][nt][2], acc[mt][nt][3]);
            } else {
                if (col < 2048) {
                    float* p0 = Cf + (size_t)row * 2048 + col;
                    *(float2*)p0 = make_float2(acc[mt][nt][0], acc[mt][nt][1]);
                    *(float2*)(p0 + (size_t)8 * 2048) = make_float2(acc[mt][nt][2], acc[mt][nt][3]);
                } else if (col < 3072) {
                    float* p0 = Kf + (size_t)row * 1024 + (col - 2048);
                    *(float2*)p0 = make_float2(acc[mt][nt][0], acc[mt][nt][1]);
                    *(float2*)(p0 + (size_t)8 * 1024) = make_float2(acc[mt][nt][2], acc[mt][nt][3]);
                } else {
                    size_t i0 = (size_t)row * 1024 + (col - 3072);
                    size_t i1 = i0 + (size_t)8 * 1024;
                    __half2 h01 = __floats2half2_rn(acc[mt][nt][0], acc[mt][nt][1]);
                    float2 f01 = __half22float2(h01);
                    __half2 l01 = __floats2half2_rn(acc[mt][nt][0] - f01.x,
                                                    acc[mt][nt][1] - f01.y);
                    __half2 h23 = __floats2half2_rn(acc[mt][nt][2], acc[mt][nt][3]);
                    float2 f23 = __half22float2(h23);
                    __half2 l23 = __floats2half2_rn(acc[mt][nt][2] - f23.x,
                                                    acc[mt][nt][3] - f23.y);
                    *(__half2*)(Ch + i0) = h01; *(__half2*)(Cl + i0) = l01;
                    *(__half2*)(Ch + i1) = h23; *(__half2*)(Cl + i1) = l23;
                }
            }
        }
    }
}

// ============================================================
// RMSNorm + RoPE (table-based), q and k in ONE launch.
// grid.y: 0..HH-1 -> q head, HH..HH+HHK-1 -> k head.
// ============================================================
__global__ void norm_rope_all(const float* __restrict__ inq, const float* __restrict__ ink,
                              __half* __restrict__ qh, __half* __restrict__ ql,
                              __half* __restrict__ kh, __half* __restrict__ kl,
                              const float* __restrict__ qw, const float* __restrict__ kw,
                              const float* __restrict__ ct, const float* __restrict__ st) {
    const int tok = blockIdx.x;
    const int hy  = blockIdx.y;
    const int s   = tok & (SS - 1);
    const int d   = threadIdx.x;

    const bool isq = hy < HH;
    const int h       = isq ? hy : hy - HH;
    const int nheads  = isq ? HH : HHK;
    const float* in   = isq ? inq : ink;
    const float* w    = isq ? qw : kw;
    __half* oh        = isq ? qh : kh;
    __half* ol        = isq ? ql : kl;
    const float oscale = isq ? 0.08838834764831845f : 1.0f;

    const float* p = in + ((size_t)tok * nheads + h) * HD;
    float v = p[d];

    float ss = v * v;
    #pragma unroll
    for (int m = 16; m > 0; m >>= 1) ss += __shfl_xor_sync(0xffffffffu, ss, m);
    __shared__ float wsum[4];
    __shared__ float vals[HD];
    if ((d & 31) == 0) wsum[d >> 5] = ss;
    __syncthreads();
    float tot = wsum[0] + wsum[1] + wsum[2] + wsum[3];
    float r = rsqrtf(tot * (1.0f / 128.0f) + 1e-6f);
    float xn = v * r * w[d];
    vals[d] = xn;
    __syncthreads();

    int i = d & 63;
    float cs = ct[s * 64 + i];
    float sn = st[s * 64 + i];
    float o;
    if (d < 64) o = vals[d] * cs - vals[d + 64] * sn;
    else        o = vals[d] * cs + vals[d - 64] * sn;
    o *= oscale;

    __half hv = __float2half_rn(o);
    __half lv = __float2half_rn(o - __half2float(hv));
    size_t idx = ((size_t)tok * nheads + h) * HD + d;
    oh[idx] = hv;
    ol[idx] = lv;
}

// ============================================================
// Flash attention (unchanged from R9): HMMA fp16-split, causal,
// GQA-fused, double-buffered K/V. smem 192KB.
// ============================================================
#define FLASH_SMEM 196608
#define SWF(r, a) ((uint32_t)((r) * 256 + ((((a) ^ (r)) & 7) | ((a) & 8)) * 16))

__global__ __launch_bounds__(256)
void flash_h(const __half* __restrict__ Qh, const __half* __restrict__ Ql,
             const __half* __restrict__ Kh, const __half* __restrict__ Kl,
             const __half* __restrict__ Vh, const __half* __restrict__ Vl,
             __half* __restrict__ Oh, __half* __restrict__ Ol) {
    extern __shared__ char smc[];
    const uint32_t sb = smem_u32(smc);
    const int qt = gridDim.x - 1 - blockIdx.x;
    const int kvh = blockIdx.y, b = blockIdx.z;
    const int tid = threadIdx.x, lane = tid & 31, wid = tid >> 5;
    const int g = lane >> 2, t4 = lane & 3;
    const int q0 = qt * 64;
    const int lr16 = lane & 15, lh = lane >> 4;
    const int wq4 = wid & 3;
    const int hsel = wid >> 2;
    const int h = 2 * kvh + hsel;

    const uint32_t QH = sb, QL = sb + 32768;
    const uint32_t KV0 = sb + 65536;

    {
        #pragma unroll
        for (int i = 0; i < 8; ++i) {
            int pos = tid + i * 256;
            int r = pos >> 4, a = pos & 15;
            int head = 2 * kvh + (r >> 6);
            int qrow = r & 63;
            uint32_t so = SWF(r, a);
            size_t go = (((size_t)(b * SS + q0 + qrow)) * HH + head) * HD + a * 8;
            CP16(QH + so, Qh + go);
            CP16(QL + so, Ql + go);
        }
        CP_COMMIT();
    }

    auto issue_kv = [&](int kt, int buf) {
        const uint32_t base = KV0 + buf * 65536;
        const int k0 = kt * 64;
        #pragma unroll
        for (int i = 0; i < 4; ++i) {
            int pos = tid + i * 256;
            int r = pos >> 4, a = pos & 15;
            uint32_t so = SWF(r, a);
            size_t go = (((size_t)(b * SS + k0 + r)) * HHK + kvh) * HD + a * 8;
            CP16(base + so,         Kh + go);
            CP16(base + 16384 + so, Kl + go);
            CP16(base + 32768 + so, Vh + go);
            CP16(base + 49152 + so, Vl + go);
        }
        CP_COMMIT();
    };

    issue_kv(0, 0);

    float oacc[16][4];
    #pragma unroll
    for (int nt = 0; nt < 16; ++nt)
        #pragma unroll
        for (int e = 0; e < 4; ++e) oacc[nt][e] = 0.f;
    float m0 = -INFINITY, m1 = -INFINITY, l0 = 0.f, l1 = 0.f;

    for (int kt = 0; kt <= qt; ++kt) {
        const int buf = kt & 1;
        const uint32_t KB = KV0 + buf * 65536;

        __syncthreads();
        if (kt < qt) { issue_kv(kt + 1, 1 - buf); CP_WAIT1(); }
        else         { CP_WAIT0(); }
        __syncthreads();

        float sacc[8][4];
        #pragma unroll
        for (int j = 0; j < 8; ++j)
            #pragma unroll
            for (int e = 0; e < 4; ++e) sacc[j][e] = 0.f;

        #pragma unroll
        for (int ks = 0; ks < 8; ++ks) {
            uint32_t qa[4], ql_[4];
            {
                int row = wid * 16 + lr16;
                int atom = 2 * ks + lh;
                uint32_t so = SWF(row, atom);
                ldsm4(qa, QH + so);
                ldsm4(ql_, QL + so);
            }
            uint32_t kf[4][4], kg[4][4];
            #pragma unroll
            for (int u = 0; u < 4; ++u) {
                int row = u * 16 + lr16;
                int atom = 2 * ks + lh;
                uint32_t so = SWF(row, atom);
                ldsm4(kf[u], KB + so);
                ldsm4(kg[u], KB + 16384 + so);
            }
            #pragma unroll
            for (int j = 0; j < 8; ++j) {
                const int u = j >> 1, s2 = j & 1;
                mma16816(sacc[j], qa,  kf[u][s2], kf[u][s2 + 2]);
                mma16816(sacc[j], qa,  kg[u][s2], kg[u][s2 + 2]);
                mma16816(sacc[j], ql_, kf[u][s2], kf[u][s2 + 2]);
            }
        }

        if (kt == qt) {
            #pragma unroll
            for (int j = 0; j < 8; ++j) {
                int colb = 8 * j + 2 * t4;
                int row0 = wq4 * 16 + g, row1 = row0 + 8;
                if (colb     > row0) sacc[j][0] = -1e30f;
                if (colb + 1 > row0) sacc[j][1] = -1e30f;
                if (colb     > row1) sacc[j][2] = -1e30f;
                if (colb + 1 > row1) sacc[j][3] = -1e30f;
            }
        }

        float mx0 = -INFINITY, mx1 = -INFINITY;
        #pragma unroll
        for (int j = 0; j < 8; ++j) {
            mx0 = fmaxf(mx0, fmaxf(sacc[j][0], sacc[j][1]));
            mx1 = fmaxf(mx1, fmaxf(sacc[j][2], sacc[j][3]));
        }
        mx0 = fmaxf(mx0, __shfl_xor_sync(0xffffffffu, mx0, 1));
        mx0 = fmaxf(mx0, __shfl_xor_sync(0xffffffffu, mx0, 2));
        mx1 = fmaxf(mx1, __shfl_xor_sync(0xffffffffu, mx1, 1));
        mx1 = fmaxf(mx1, __shfl_xor_sync(0xffffffffu, mx1, 2));
        float mn0 = fmaxf(m0, mx0), mn1 = fmaxf(m1, mx1);
        float al0 = __expf(m0 - mn0), al1 = __expf(m1 - mn1);
        m0 = mn0; m1 = mn1;

        float s0 = 0.f, s1 = 0.f;
        uint32_t pa[4][4];
        #pragma unroll
        for (int j = 0; j < 8; ++j) {
            float p0 = __expf(sacc[j][0] - mn0), p1 = __expf(sacc[j][1] - mn0);
            float p2 = __expf(sacc[j][2] - mn1), p3 = __expf(sacc[j][3] - mn1);
            __half2 hA = __floats2half2_rn(p0, p1);
            __half2 hB = __floats2half2_rn(p2, p3);
            float2 fA = __half22float2(hA), fB = __half22float2(hB);
            s0 += fA.x + fA.y;
            s1 += fB.x + fB.y;
            pa[j >> 1][(j & 1) * 2 + 0] = *(uint32_t*)&hA;
            pa[j >> 1][(j & 1) * 2 + 1] = *(uint32_t*)&hB;
        }
        s0 += __shfl_xor_sync(0xffffffffu, s0, 1);
        s0 += __shfl_xor_sync(0xffffffffu, s0, 2);
        s1 += __shfl_xor_sync(0xffffffffu, s1, 1);
        s1 += __shfl_xor_sync(0xffffffffu, s1, 2);
        l0 = l0 * al0 + s0;
        l1 = l1 * al1 + s1;
        #pragma unroll
        for (int nt = 0; nt < 16; ++nt) {
            oacc[nt][0] *= al0; oacc[nt][1] *= al0;
            oacc[nt][2] *= al1; oacc[nt][3] *= al1;
        }

        #pragma unroll
        for (int kc = 0; kc < 4; ++kc) {
            uint32_t vf[8][4];
            #pragma unroll
            for (int u = 0; u < 8; ++u) {
                int row = 16 * kc + lr16;
                int atom = 2 * u + lh;
                ldsm4t(vf[u], KB + 32768 + SWF(row, atom));
            }
            #pragma unroll
            for (int nt = 0; nt < 16; ++nt) {
                const int u = nt >> 1, s2 = (nt & 1) * 2;
                mma16816(oacc[nt], pa[kc], vf[u][s2], vf[u][s2 + 1]);
            }
            #pragma unroll
            for (int u = 0; u < 8; ++u) {
                int row = 16 * kc + lr16;
                int atom = 2 * u + lh;
                ldsm4t(vf[u], KB + 49152 + SWF(row, atom));
            }
            #pragma unroll
            for (int nt = 0; nt < 16; ++nt) {
                const int u = nt >> 1, s2 = (nt & 1) * 2;
                mma16816(oacc[nt], pa[kc], vf[u][s2], vf[u][s2 + 1]);
            }
        }
    }

    const float il0 = 1.0f / l0, il1 = 1.0f / l1;
    const int gr0 = q0 + wq4 * 16 + g;
    const int gr1 = gr0 + 8;
    #pragma unroll
    for (int nt = 0; nt < 16; ++nt) {
        float o0 = oacc[nt][0] * il0, o1 = oacc[nt][1] * il0;
        float o2 = oacc[nt][2] * il1, o3 = oacc[nt][3] * il1;
        int col = nt * 8 + t4 * 2;
        size_t i0 = ((size_t)(b * SS + gr0) * HH + h) * HD + col;
        size_t i1 = ((size_t)(b * SS + gr1) * HH + h) * HD + col;
        __half2 h01 = __floats2half2_rn(o0, o1);
        float2 f01 = __half22float2(h01);
        __half2 l01 = __floats2half2_rn(o0 - f01.x, o1 - f01.y);
        __half2 h23 = __floats2half2_rn(o2, o3);
        float2 f23 = __half22float2(h23);
        __half2 l23 = __floats2half2_rn(o2 - f23.x, o3 - f23.y);
        *(__half2*)(Oh + i0) = h01; *(__half2*)(Ol + i0) = l01;
        *(__half2*)(Oh + i1) = h23; *(__half2*)(Ol + i1) = l23;
    }
}

// ============================================================
// kernel_launch
// ============================================================
extern "C" void kernel_launch(void* const* d_in, const int* in_sizes, int n_in,
                              void* d_out, int out_size) {
    const float* x   = (const float*)d_in[0];
    const float* wq  = (const float*)d_in[1];
    const float* wk  = (const float*)d_in[2];
    const float* wv  = (const float*)d_in[3];
    const float* wo  = (const float*)d_in[4];
    const float* qnw = (const float*)d_in[5];
    const float* knw = (const float*)d_in[6];
    float* out = (float*)d_out;

    float *gq, *gk, *ct, *st;
    __half *xh, *xl, *wqkv, *woh;
    __half *qh, *ql, *kh, *kl, *vh, *vl, *ah, *al;
    cudaGetSymbolAddress((void**)&gq, g_q);
    cudaGetSymbolAddress((void**)&gk, g_k);
    cudaGetSymbolAddress((void**)&ct, g_ct);
    cudaGetSymbolAddress((void**)&st, g_st);
    cudaGetSymbolAddress((void**)&xh, g_xh);   cudaGetSymbolAddress((void**)&xl, g_xl);
    cudaGetSymbolAddress((void**)&wqkv, g_wqkv);
    cudaGetSymbolAddress((void**)&woh, g_woh);
    cudaGetSymbolAddress((void**)&qh, g_qh);   cudaGetSymbolAddress((void**)&ql, g_ql);
    cudaGetSymbolAddress((void**)&kh, g_kh);   cudaGetSymbolAddress((void**)&kl, g_kl);
    cudaGetSymbolAddress((void**)&vh, g_vh);   cudaGetSymbolAddress((void**)&vl, g_vl);
    cudaGetSymbolAddress((void**)&ah, g_ah);   cudaGetSymbolAddress((void**)&al, g_al);

    cudaFuncSetAttribute(gemm_h, cudaFuncAttributeMaxDynamicSharedMemorySize, GEMM_SMEM);
    cudaFuncSetAttribute(flash_h, cudaFuncAttributeMaxDynamicSharedMemorySize, FLASH_SMEM);

    // prep
    rope_table<<<(SS * 64) / 256, 256>>>(ct, st);
    split_fp16<<<(MM*DD/4 + 255)/256, 256>>>(x, xh, xl, MM*DD/4);
    cast_all<<<(W_Q4 + 2*W_K4 + W_O4) / 256, 256>>>(wq, wk, wv, wo, wqkv, woh);

    // fused QKV projection (N = 4096), segmented epilogue
    gemm_h<<<dim3(32, MM/128), 128, GEMM_SMEM>>>(
        xh, xl, wqkv, gq, gk, vh, vl, MM, 4096, DD, 2);

    // RMSNorm + RoPE (q and k fused into one launch)
    norm_rope_all<<<dim3(MM, HH + HHK), HD>>>(gq, gk, qh, ql, kh, kl,
                                              qnw, knw, ct, st);

    // causal flash attention
    flash_h<<<dim3(SS/64, HHK, BB), 256, FLASH_SMEM>>>(qh, ql, kh, kl, vh, vl, ah, al);

    // output projection
    gemm_h<<<dim3(DD/128, MM/128), 128, GEMM_SMEM>>>(
        ah, al, woh, out, nullptr, nullptr, nullptr, MM, DD, DD, 0);
}

// round 12
// speedup vs baseline: 1.0018x; 1.0018x over previous
#include <cuda_runtime.h>
#include <cuda_fp16.h>
#include <math.h>
#include <stdint.h>

// ---------------- problem constants ----------------
#define BB   2
#define SS   2048
#define DD   2048
#define HH   16
#define HHK  8
#define HD   128
#define MM   (BB*SS)          // 4096 tokens

// ---------------- scratch (device globals) ----------------
__device__ __align__(256) float  g_q[MM * HH * HD];
__device__ __align__(256) float  g_k[MM * HHK * HD];
__device__ __align__(256) __half g_xh[MM * DD],     g_xl[MM * DD];
__device__ __align__(256) __half g_wqkv[(HH + 2 * HHK) * HD * DD];
__device__ __align__(256) __half g_woh[DD * HH * HD];
__device__ __align__(256) __half g_qh[MM*HH*HD],    g_ql[MM*HH*HD];
__device__ __align__(256) __half g_kh[MM*HHK*HD],   g_kl[MM*HHK*HD];
__device__ __align__(256) __half g_vh[MM*HHK*HD],   g_vl[MM*HHK*HD];
__device__ __align__(256) __half g_ah[MM*HH*HD],    g_al[MM*HH*HD];
__device__ __align__(256) float  g_ct[SS * 64],     g_st[SS * 64];

// ============================================================
// helpers
// ============================================================
__device__ __forceinline__ uint32_t smem_u32(const void* p) {
    uint32_t a;
    asm("{ .reg .u64 t; cvta.to.shared.u64 t, %1; cvt.u32.u64 %0, t; }"
        : "=r"(a) : "l"(p));
    return a;
}
__device__ __forceinline__ void ldsm4(uint32_t* r, uint32_t addr) {
    asm volatile("ldmatrix.sync.aligned.m8n8.x4.shared.b16 {%0,%1,%2,%3}, [%4];"
                 : "=r"(r[0]), "=r"(r[1]), "=r"(r[2]), "=r"(r[3]) : "r"(addr));
}
__device__ __forceinline__ void ldsm4t(uint32_t* r, uint32_t addr) {
    asm volatile("ldmatrix.sync.aligned.m8n8.x4.trans.shared.b16 {%0,%1,%2,%3}, [%4];"
                 : "=r"(r[0]), "=r"(r[1]), "=r"(r[2]), "=r"(r[3]) : "r"(addr));
}
__device__ __forceinline__ void mma16816(float* c, const uint32_t* a,
                                         uint32_t b0, uint32_t b1) {
    asm volatile(
        "mma.sync.aligned.m16n8k16.row.col.f32.f16.f16.f32 "
        "{%0,%1,%2,%3}, {%4,%5,%6,%7}, {%8,%9}, {%0,%1,%2,%3};"
        : "+f"(c[0]), "+f"(c[1]), "+f"(c[2]), "+f"(c[3])
        : "r"(a[0]), "r"(a[1]), "r"(a[2]), "r"(a[3]), "r"(b0), "r"(b1));
}
#define CP16(dst, src) asm volatile("cp.async.cg.shared.global [%0], [%1], 16;" \
                                    :: "r"(dst), "l"(src))
#define CP_COMMIT()    asm volatile("cp.async.commit_group;" ::: "memory")
#define CP_WAIT0()     asm volatile("cp.async.wait_group 0;" ::: "memory")
#define CP_WAIT1()     asm volatile("cp.async.wait_group 1;" ::: "memory")

// ============================================================
// small prep kernels
// ============================================================
__global__ void split_fp16(const float* __restrict__ src, __half* __restrict__ hi,
                           __half* __restrict__ lo, int n4) {
    int i = blockIdx.x * blockDim.x + threadIdx.x;
    if (i >= n4) return;
    float4 v = ((const float4*)src)[i];
    __half2 h01 = __floats2half2_rn(v.x, v.y);
    __half2 h23 = __floats2half2_rn(v.z, v.w);
    float2 f01 = __half22float2(h01), f23 = __half22float2(h23);
    __half2 l01 = __floats2half2_rn(v.x - f01.x, v.y - f01.y);
    __half2 l23 = __floats2half2_rn(v.z - f23.x, v.w - f23.y);
    ((__half2*)hi)[2*i] = h01; ((__half2*)hi)[2*i+1] = h23;
    ((__half2*)lo)[2*i] = l01; ((__half2*)lo)[2*i+1] = l23;
}

#define W_Q4 (HH*HD*DD/4)
#define W_K4 (HHK*HD*DD/4)
#define W_O4 (DD*HH*HD/4)
__global__ void cast_all(const float* __restrict__ wq, const float* __restrict__ wk,
                         const float* __restrict__ wv, const float* __restrict__ wo,
                         __half* __restrict__ wqkv, __half* __restrict__ woh) {
    int i = blockIdx.x * blockDim.x + threadIdx.x;
    const float* src; __half* dst; int j;
    if (i < W_Q4)                { src = wq; dst = wqkv;                     j = i; }
    else if (i < W_Q4 + W_K4)    { src = wk; dst = wqkv + HH*HD*DD;          j = i - W_Q4; }
    else if (i < W_Q4 + 2*W_K4)  { src = wv; dst = wqkv + (HH+HHK)*HD*DD;    j = i - W_Q4 - W_K4; }
    else                         { src = wo; dst = woh;                      j = i - W_Q4 - 2*W_K4; }
    float4 v = ((const float4*)src)[j];
    ((__half2*)dst)[2*j]   = __floats2half2_rn(v.x, v.y);
    ((__half2*)dst)[2*j+1] = __floats2half2_rn(v.z, v.w);
}

__global__ void rope_table(float* __restrict__ ct, float* __restrict__ st) {
    int idx = blockIdx.x * blockDim.x + threadIdx.x;   // SS*64
    int s = idx >> 6, i = idx & 63;
    float inv_freq = powf(1.0e6f, -(float)i * (1.0f / 64.0f));
    float sn, cs;
    sincosf((float)s * inv_freq, &sn, &cs);
    ct[idx] = cs; st[idx] = sn;
}

// ============================================================
// HMMA fp16x2-split GEMM: C = A*W^T, A split hi/lo, W fp16.
// CTA 128x128, BK=32, **128 threads, 4 warps, warp tile 64x64**.
// 3-stage cp.async (72KB).  epi 0: fp32; epi 2: fused QKV epilogue.
// ============================================================
#define GEMM_SMEM (3 * 24576)

__global__ __launch_bounds__(128)
void gemm_h(const __half* __restrict__ Ah, const __half* __restrict__ Al,
            const __half* __restrict__ Bh,
            float* __restrict__ Cf, float* __restrict__ Kf,
            __half* __restrict__ Ch, __half* __restrict__ Cl,
            int M, int N, int K, int epi) {
    extern __shared__ char smc[];
    const uint32_t sb = smem_u32(smc);
    const int tid  = threadIdx.x;
    const int lane = tid & 31;
    const int wid  = tid >> 5;          // 0..3
    const int wm   = wid & 1;           // 2 warps over M (64 rows)
    const int wn   = wid >> 1;          // 2 warps over N (64 cols)
    const int brow = blockIdx.y * 128;
    const int bcol = blockIdx.x * 128;

    const __half* Agh = Ah + (size_t)brow * K;
    const __half* Agl = Al + (size_t)brow * K;
    const __half* Bgh = Bh + (size_t)bcol * K;

    const int lr = tid >> 2;            // 0..31
    const int kq = tid & 3;

    auto issue = [&](int stage, int k0) {
        const uint32_t stb = sb + stage * 24576;
        #pragma unroll
        for (int i = 0; i < 4; ++i) {
            int r = lr + i * 32;
            uint32_t so = (uint32_t)(r * 64 + ((kq ^ ((r >> 1) & 3)) * 16));
            size_t go = (size_t)r * K + k0 + kq * 8;
            CP16(stb + so,         Agh + go);
            CP16(stb + 8192 + so,  Agl + go);
            CP16(stb + 16384 + so, Bgh + go);
        }
    };

    float acc[4][8][4];
    #pragma unroll
    for (int mt = 0; mt < 4; ++mt)
        #pragma unroll
        for (int nt = 0; nt < 8; ++nt)
            #pragma unroll
            for (int e = 0; e < 4; ++e) acc[mt][nt][e] = 0.f;

    const int nk = K >> 5;
    issue(0, 0);  CP_COMMIT();
    issue(1, 32); CP_COMMIT();

    const int lrow16 = lane & 15;
    const int lhalf  = lane >> 4;

    for (int c = 0; c < nk; ++c) {
        CP_WAIT1();
        __syncthreads();
        const uint32_t stb = sb + (c % 3) * 24576;

        #pragma unroll
        for (int ks = 0; ks < 2; ++ks) {
            uint32_t ah[4][4], al[4][4], bh[4][4];
            #pragma unroll
            for (int mt = 0; mt < 4; ++mt) {
                int row = wm * 64 + mt * 16 + lrow16;
                int atom = (ks * 2 + lhalf) ^ ((row >> 1) & 3);
                uint32_t ad = stb + (uint32_t)(row * 64 + atom * 16);
                ldsm4(ah[mt], ad);
                ldsm4(al[mt], ad + 8192);
            }
            #pragma unroll
            for (int g2 = 0; g2 < 4; ++g2) {
                int row = wn * 64 + g2 * 16 + lrow16;
                int atom = (ks * 2 + lhalf) ^ ((row >> 1) & 3);
                uint32_t ad = stb + 16384 + (uint32_t)(row * 64 + atom * 16);
                ldsm4(bh[g2], ad);
            }
            #pragma unroll
            for (int mt = 0; mt < 4; ++mt)
                #pragma unroll
                for (int nt = 0; nt < 8; ++nt) {
                    const int g2 = nt >> 1, s2 = nt & 1;
                    mma16816(acc[mt][nt], ah[mt], bh[g2][s2], bh[g2][s2 + 2]);
                    mma16816(acc[mt][nt], al[mt], bh[g2][s2], bh[g2][s2 + 2]);
                }
        }
        if (c + 2 < nk) issue((c + 2) % 3, (c + 2) << 5);
        CP_COMMIT();
    }

    // ---- epilogue ----
    #pragma unroll
    for (int mt = 0; mt < 4; ++mt) {
        int row = brow + wm * 64 + mt * 16 + (lane >> 2);
        #pragma unroll
        for (int nt = 0; nt < 8; ++nt) {
            int col = bcol + wn * 64 + nt * 8 + (lane & 3) * 2;
            if (epi == 0) {
                float* p0 = Cf + (size_t)row * N + col;
                *(float2*)p0 = make_float2(acc[mt][nt][0], acc[mt][nt][1]);
                *(float2*)(p0 + (size_t)8 * N) = make_float2(acc[mt][nt][2], acc[mt][nt][3]);
            } else {
                if (col < 2048) {
                    float* p0 = Cf + (size_t)row * 2048 + col;
                    *(float2*)p0 = make_float2(acc[mt][nt][0], acc[mt][nt][1]);
                    *(float2*)(p0 + (size_t)8 * 2048) = make_float2(acc[mt][nt][2], acc[mt][nt][3]);
                } else if (col < 3072) {
                    float* p0 = Kf + (size_t)row * 1024 + (col - 2048);
                    *(float2*)p0 = make_float2(acc[mt][nt][0], acc[mt][nt][1]);
                    *(float2*)(p0 + (size_t)8 * 1024) = make_float2(acc[mt][nt][2], acc[mt][nt][3]);
                } else {
                    size_t i0 = (size_t)row * 1024 + (col - 3072);
                    size_t i1 = i0 + (size_t)8 * 1024;
                    __half2 h01 = __floats2half2_rn(acc[mt][nt][0], acc[mt][nt][1]);
                    float2 f01 = __half22float2(h01);
                    __half2 l01 = __floats2half2_rn(acc[mt][nt][0] - f01.x,
                                                    acc[mt][nt][1] - f01.y);
                    __half2 h23 = __floats2half2_rn(acc[mt][nt][2], acc[mt][nt][3]);
                    float2 f23 = __half22float2(h23);
                    __half2 l23 = __floats2half2_rn(acc[mt][nt][2] - f23.x,
                                                    acc[mt][nt][3] - f23.y);
                    *(__half2*)(Ch + i0) = h01; *(__half2*)(Cl + i0) = l01;
                    *(__half2*)(Ch + i1) = h23; *(__half2*)(Cl + i1) = l23;
                }
            }
        }
    }
}

// ============================================================
// RMSNorm + RoPE (table-based), q and k in ONE launch.
// grid.y: 0..HH-1 -> q head, HH..HH+HHK-1 -> k head.
// ============================================================
__global__ void norm_rope_all(const float* __restrict__ inq, const float* __restrict__ ink,
                              __half* __restrict__ qh, __half* __restrict__ ql,
                              __half* __restrict__ kh, __half* __restrict__ kl,
                              const float* __restrict__ qw, const float* __restrict__ kw,
                              const float* __restrict__ ct, const float* __restrict__ st) {
    const int tok = blockIdx.x;
    const int hy  = blockIdx.y;
    const int s   = tok & (SS - 1);
    const int d   = threadIdx.x;

    const bool isq = hy < HH;
    const int h       = isq ? hy : hy - HH;
    const int nheads  = isq ? HH : HHK;
    const float* in   = isq ? inq : ink;
    const float* w    = isq ? qw : kw;
    __half* oh        = isq ? qh : kh;
    __half* ol        = isq ? ql : kl;
    const float oscale = isq ? 0.08838834764831845f : 1.0f;

    const float* p = in + ((size_t)tok * nheads + h) * HD;
    float v = p[d];

    float ss = v * v;
    #pragma unroll
    for (int m = 16; m > 0; m >>= 1) ss += __shfl_xor_sync(0xffffffffu, ss, m);
    __shared__ float wsum[4];
    __shared__ float vals[HD];
    if ((d & 31) == 0) wsum[d >> 5] = ss;
    __syncthreads();
    float tot = wsum[0] + wsum[1] + wsum[2] + wsum[3];
    float r = rsqrtf(tot * (1.0f / 128.0f) + 1e-6f);
    float xn = v * r * w[d];
    vals[d] = xn;
    __syncthreads();

    int i = d & 63;
    float cs = ct[s * 64 + i];
    float sn = st[s * 64 + i];
    float o;
    if (d < 64) o = vals[d] * cs - vals[d + 64] * sn;
    else        o = vals[d] * cs + vals[d - 64] * sn;
    o *= oscale;

    __half hv = __float2half_rn(o);
    __half lv = __float2half_rn(o - __half2float(hv));
    size_t idx = ((size_t)tok * nheads + h) * HD + d;
    oh[idx] = hv;
    ol[idx] = lv;
}

// ============================================================
// Flash attention (unchanged from R9): HMMA fp16-split, causal,
// GQA-fused, double-buffered K/V. smem 192KB.
// ============================================================
#define FLASH_SMEM 196608
#define SWF(r, a) ((uint32_t)((r) * 256 + ((((a) ^ (r)) & 7) | ((a) & 8)) * 16))

__global__ __launch_bounds__(256)
void flash_h(const __half* __restrict__ Qh, const __half* __restrict__ Ql,
             const __half* __restrict__ Kh, const __half* __restrict__ Kl,
             const __half* __restrict__ Vh, const __half* __restrict__ Vl,
             __half* __restrict__ Oh, __half* __restrict__ Ol) {
    extern __shared__ char smc[];
    const uint32_t sb = smem_u32(smc);
    const int qt = gridDim.x - 1 - blockIdx.x;
    const int kvh = blockIdx.y, b = blockIdx.z;
    const int tid = threadIdx.x, lane = tid & 31, wid = tid >> 5;
    const int g = lane >> 2, t4 = lane & 3;
    const int q0 = qt * 64;
    const int lr16 = lane & 15, lh = lane >> 4;
    const int wq4 = wid & 3;
    const int hsel = wid >> 2;
    const int h = 2 * kvh + hsel;

    const uint32_t QH = sb, QL = sb + 32768;
    const uint32_t KV0 = sb + 65536;

    {
        #pragma unroll
        for (int i = 0; i < 8; ++i) {
            int pos = tid + i * 256;
            int r = pos >> 4, a = pos & 15;
            int head = 2 * kvh + (r >> 6);
            int qrow = r & 63;
            uint32_t so = SWF(r, a);
            size_t go = (((size_t)(b * SS + q0 + qrow)) * HH + head) * HD + a * 8;
            CP16(QH + so, Qh + go);
            CP16(QL + so, Ql + go);
        }
        CP_COMMIT();
    }

    auto issue_kv = [&](int kt, int buf) {
        const uint32_t base = KV0 + buf * 65536;
        const int k0 = kt * 64;
        #pragma unroll
        for (int i = 0; i < 4; ++i) {
            int pos = tid + i * 256;
            int r = pos >> 4, a = pos & 15;
            uint32_t so = SWF(r, a);
            size_t go = (((size_t)(b * SS + k0 + r)) * HHK + kvh) * HD + a * 8;
            CP16(base + so,         Kh + go);
            CP16(base + 16384 + so, Kl + go);
            CP16(base + 32768 + so, Vh + go);
            CP16(base + 49152 + so, Vl + go);
        }
        CP_COMMIT();
    };

    issue_kv(0, 0);

    float oacc[16][4];
    #pragma unroll
    for (int nt = 0; nt < 16; ++nt)
        #pragma unroll
        for (int e = 0; e < 4; ++e) oacc[nt][e] = 0.f;
    float m0 = -INFINITY, m1 = -INFINITY, l0 = 0.f, l1 = 0.f;

    for (int kt = 0; kt <= qt; ++kt) {
        const int buf = kt & 1;
        const uint32_t KB = KV0 + buf * 65536;

        __syncthreads();
        if (kt < qt) { issue_kv(kt + 1, 1 - buf); CP_WAIT1(); }
        else         { CP_WAIT0(); }
        __syncthreads();

        float sacc[8][4];
        #pragma unroll
        for (int j = 0; j < 8; ++j)
            #pragma unroll
            for (int e = 0; e < 4; ++e) sacc[j][e] = 0.f;

        #pragma unroll
        for (int ks = 0; ks < 8; ++ks) {
            uint32_t qa[4], ql_[4];
            {
                int row = wid * 16 + lr16;
                int atom = 2 * ks + lh;
                uint32_t so = SWF(row, atom);
                ldsm4(qa, QH + so);
                ldsm4(ql_, QL + so);
            }
            uint32_t kf[4][4], kg[4][4];
            #pragma unroll
            for (int u = 0; u < 4; ++u) {
                int row = u * 16 + lr16;
                int atom = 2 * ks + lh;
                uint32_t so = SWF(row, atom);
                ldsm4(kf[u], KB + so);
                ldsm4(kg[u], KB + 16384 + so);
            }
            #pragma unroll
            for (int j = 0; j < 8; ++j) {
                const int u = j >> 1, s2 = j & 1;
                mma16816(sacc[j], qa,  kf[u][s2], kf[u][s2 + 2]);
                mma16816(sacc[j], qa,  kg[u][s2], kg[u][s2 + 2]);
                mma16816(sacc[j], ql_, kf[u][s2], kf[u][s2 + 2]);
            }
        }

        if (kt == qt) {
            #pragma unroll
            for (int j = 0; j < 8; ++j) {
                int colb = 8 * j + 2 * t4;
                int row0 = wq4 * 16 + g, row1 = row0 + 8;
                if (colb     > row0) sacc[j][0] = -1e30f;
                if (colb + 1 > row0) sacc[j][1] = -1e30f;
                if (colb     > row1) sacc[j][2] = -1e30f;
                if (colb + 1 > row1) sacc[j][3] = -1e30f;
            }
        }

        float mx0 = -INFINITY, mx1 = -INFINITY;
        #pragma unroll
        for (int j = 0; j < 8; ++j) {
            mx0 = fmaxf(mx0, fmaxf(sacc[j][0], sacc[j][1]));
            mx1 = fmaxf(mx1, fmaxf(sacc[j][2], sacc[j][3]));
        }
        mx0 = fmaxf(mx0, __shfl_xor_sync(0xffffffffu, mx0, 1));
        mx0 = fmaxf(mx0, __shfl_xor_sync(0xffffffffu, mx0, 2));
        mx1 = fmaxf(mx1, __shfl_xor_sync(0xffffffffu, mx1, 1));
        mx1 = fmaxf(mx1, __shfl_xor_sync(0xffffffffu, mx1, 2));
        float mn0 = fmaxf(m0, mx0), mn1 = fmaxf(m1, mx1);
        float al0 = __expf(m0 - mn0), al1 = __expf(m1 - mn1);
        m0 = mn0; m1 = mn1;

        float s0 = 0.f, s1 = 0.f;
        uint32_t pa[4][4];
        #pragma unroll
        for (int j = 0; j < 8; ++j) {
            float p0 = __expf(sacc[j][0] - mn0), p1 = __expf(sacc[j][1] - mn0);
            float p2 = __expf(sacc[j][2] - mn1), p3 = __expf(sacc[j][3] - mn1);
            __half2 hA = __floats2half2_rn(p0, p1);
            __half2 hB = __floats2half2_rn(p2, p3);
            float2 fA = __half22float2(hA), fB = __half22float2(hB);
            s0 += fA.x + fA.y;
            s1 += fB.x + fB.y;
            pa[j >> 1][(j & 1) * 2 + 0] = *(uint32_t*)&hA;
            pa[j >> 1][(j & 1) * 2 + 1] = *(uint32_t*)&hB;
        }
        s0 += __shfl_xor_sync(0xffffffffu, s0, 1);
        s0 += __shfl_xor_sync(0xffffffffu, s0, 2);
        s1 += __shfl_xor_sync(0xffffffffu, s1, 1);
        s1 += __shfl_xor_sync(0xffffffffu, s1, 2);
        l0 = l0 * al0 + s0;
        l1 = l1 * al1 + s1;
        #pragma unroll
        for (int nt = 0; nt < 16; ++nt) {
            oacc[nt][0] *= al0; oacc[nt][1] *= al0;
            oacc[nt][2] *= al1; oacc[nt][3] *= al1;
        }

        #pragma unroll
        for (int kc = 0; kc < 4; ++kc) {
            uint32_t vf[8][4];
            #pragma unroll
            for (int u = 0; u < 8; ++u) {
                int row = 16 * kc + lr16;
                int atom = 2 * u + lh;
                ldsm4t(vf[u], KB + 32768 + SWF(row, atom));
            }
            #pragma unroll
            for (int nt = 0; nt < 16; ++nt) {
                const int u = nt >> 1, s2 = (nt & 1) * 2;
                mma16816(oacc[nt], pa[kc], vf[u][s2], vf[u][s2 + 1]);
            }
            #pragma unroll
            for (int u = 0; u < 8; ++u) {
                int row = 16 * kc + lr16;
                int atom = 2 * u + lh;
                ldsm4t(vf[u], KB + 49152 + SWF(row, atom));
            }
            #pragma unroll
            for (int nt = 0; nt < 16; ++nt) {
                const int u = nt >> 1, s2 = (nt & 1) * 2;
                mma16816(oacc[nt], pa[kc], vf[u][s2], vf[u][s2 + 1]);
            }
        }
    }

    const float il0 = 1.0f / l0, il1 = 1.0f / l1;
    const int gr0 = q0 + wq4 * 16 + g;
    const int gr1 = gr0 + 8;
    #pragma unroll
    for (int nt = 0; nt < 16; ++nt) {
        float o0 = oacc[nt][0] * il0, o1 = oacc[nt][1] * il0;
        float o2 = oacc[nt][2] * il1, o3 = oacc[nt][3] * il1;
        int col = nt * 8 + t4 * 2;
        size_t i0 = ((size_t)(b * SS + gr0) * HH + h) * HD + col;
        size_t i1 = ((size_t)(b * SS + gr1) * HH + h) * HD + col;
        __half2 h01 = __floats2half2_rn(o0, o1);
        float2 f01 = __half22float2(h01);
        __half2 l01 = __floats2half2_rn(o0 - f01.x, o1 - f01.y);
        __half2 h23 = __floats2half2_rn(o2, o3);
        float2 f23 = __half22float2(h23);
        __half2 l23 = __floats2half2_rn(o2 - f23.x, o3 - f23.y);
        *(__half2*)(Oh + i0) = h01; *(__half2*)(Ol + i0) = l01;
        *(__half2*)(Oh + i1) = h23; *(__half2*)(Ol + i1) = l23;
    }
}

// ============================================================
// kernel_launch
// ============================================================
extern "C" void kernel_launch(void* const* d_in, const int* in_sizes, int n_in,
                              void* d_out, int out_size) {
    const float* x   = (const float*)d_in[0];
    const float* wq  = (const float*)d_in[1];
    const float* wk  = (const float*)d_in[2];
    const float* wv  = (const float*)d_in[3];
    const float* wo  = (const float*)d_in[4];
    const float* qnw = (const float*)d_in[5];
    const float* knw = (const float*)d_in[6];
    float* out = (float*)d_out;

    float *gq, *gk, *ct, *st;
    __half *xh, *xl, *wqkv, *woh;
    __half *qh, *ql, *kh, *kl, *vh, *vl, *ah, *al;
    cudaGetSymbolAddress((void**)&gq, g_q);
    cudaGetSymbolAddress((void**)&gk, g_k);
    cudaGetSymbolAddress((void**)&ct, g_ct);
    cudaGetSymbolAddress((void**)&st, g_st);
    cudaGetSymbolAddress((void**)&xh, g_xh);   cudaGetSymbolAddress((void**)&xl, g_xl);
    cudaGetSymbolAddress((void**)&wqkv, g_wqkv);
    cudaGetSymbolAddress((void**)&woh, g_woh);
    cudaGetSymbolAddress((void**)&qh, g_qh);   cudaGetSymbolAddress((void**)&ql, g_ql);
    cudaGetSymbolAddress((void**)&kh, g_kh);   cudaGetSymbolAddress((void**)&kl, g_kl);
    cudaGetSymbolAddress((void**)&vh, g_vh);   cudaGetSymbolAddress((void**)&vl, g_vl);
    cudaGetSymbolAddress((void**)&ah, g_ah);   cudaGetSymbolAddress((void**)&al, g_al);

    cudaFuncSetAttribute(gemm_h, cudaFuncAttributeMaxDynamicSharedMemorySize, GEMM_SMEM);
    cudaFuncSetAttribute(flash_h, cudaFuncAttributeMaxDynamicSharedMemorySize, FLASH_SMEM);

    // prep
    rope_table<<<(SS * 64) / 256, 256>>>(ct, st);
    split_fp16<<<(MM*DD/4 + 255)/256, 256>>>(x, xh, xl, MM*DD/4);
    cast_all<<<(W_Q4 + 2*W_K4 + W_O4) / 256, 256>>>(wq, wk, wv, wo, wqkv, woh);

    // fused QKV projection (N = 4096), segmented epilogue
    gemm_h<<<dim3(32, MM/128), 128, GEMM_SMEM>>>(
        xh, xl, wqkv, gq, gk, vh, vl, MM, 4096, DD, 2);

    // RMSNorm + RoPE (q and k fused into one launch)
    norm_rope_all<<<dim3(MM, HH + HHK), HD>>>(gq, gk, qh, ql, kh, kl,
                                              qnw, knw, ct, st);

    // causal flash attention
    flash_h<<<dim3(SS/64, HHK, BB), 256, FLASH_SMEM>>>(qh, ql, kh, kl, vh, vl, ah, al);

    // output projection
    gemm_h<<<dim3(DD/128, MM/128), 128, GEMM_SMEM>>>(
        ah, al, woh, out, nullptr, nullptr, nullptr, MM, DD, DD, 0);
}

// round 13
// speedup vs baseline: 1.0507x; 1.0488x over previous
#include <cuda_runtime.h>
#include <cuda_fp16.h>
#include <math.h>
#include <stdint.h>

// ---------------- problem constants ----------------
#define BB   2
#define SS   2048
#define DD   2048
#define HH   16
#define HHK  8
#define HD   128
#define MM   (BB*SS)          // 4096 tokens

// ---------------- scratch (device globals) ----------------
__device__ __align__(256) float  g_q[MM * HH * HD];
__device__ __align__(256) float  g_k[MM * HHK * HD];
__device__ __align__(256) __half g_xh[MM * DD],     g_xl[MM * DD];
__device__ __align__(256) __half g_wqkv[(HH + 2 * HHK) * HD * DD];
__device__ __align__(256) __half g_woh[DD * HH * HD];
__device__ __align__(256) __half g_qh[MM*HH*HD],    g_ql[MM*HH*HD];
__device__ __align__(256) __half g_kh[MM*HHK*HD],   g_kl[MM*HHK*HD];
__device__ __align__(256) __half g_vh[MM*HHK*HD],   g_vl[MM*HHK*HD];
__device__ __align__(256) __half g_ah[MM*HH*HD],    g_al[MM*HH*HD];
__device__ __align__(256) float  g_ct[SS * 64],     g_st[SS * 64];

// ============================================================
// helpers
// ============================================================
__device__ __forceinline__ uint32_t smem_u32(const void* p) {
    uint32_t a;
    asm("{ .reg .u64 t; cvta.to.shared.u64 t, %1; cvt.u32.u64 %0, t; }"
        : "=r"(a) : "l"(p));
    return a;
}
__device__ __forceinline__ void ldsm4(uint32_t* r, uint32_t addr) {
    asm volatile("ldmatrix.sync.aligned.m8n8.x4.shared.b16 {%0,%1,%2,%3}, [%4];"
                 : "=r"(r[0]), "=r"(r[1]), "=r"(r[2]), "=r"(r[3]) : "r"(addr));
}
__device__ __forceinline__ void ldsm4t(uint32_t* r, uint32_t addr) {
    asm volatile("ldmatrix.sync.aligned.m8n8.x4.trans.shared.b16 {%0,%1,%2,%3}, [%4];"
                 : "=r"(r[0]), "=r"(r[1]), "=r"(r[2]), "=r"(r[3]) : "r"(addr));
}
__device__ __forceinline__ void mma16816(float* c, const uint32_t* a,
                                         uint32_t b0, uint32_t b1) {
    asm volatile(
        "mma.sync.aligned.m16n8k16.row.col.f32.f16.f16.f32 "
        "{%0,%1,%2,%3}, {%4,%5,%6,%7}, {%8,%9}, {%0,%1,%2,%3};"
        : "+f"(c[0]), "+f"(c[1]), "+f"(c[2]), "+f"(c[3])
        : "r"(a[0]), "r"(a[1]), "r"(a[2]), "r"(a[3]), "r"(b0), "r"(b1));
}
#define CP16(dst, src) asm volatile("cp.async.cg.shared.global [%0], [%1], 16;" \
                                    :: "r"(dst), "l"(src))
#define CP_COMMIT()    asm volatile("cp.async.commit_group;" ::: "memory")
#define CP_WAIT0()     asm volatile("cp.async.wait_group 0;" ::: "memory")
#define CP_WAIT1()     asm volatile("cp.async.wait_group 1;" ::: "memory")

// ============================================================
// small prep kernels
// ============================================================
__global__ void split_fp16(const float* __restrict__ src, __half* __restrict__ hi,
                           __half* __restrict__ lo, int n4) {
    int i = blockIdx.x * blockDim.x + threadIdx.x;
    if (i >= n4) return;
    float4 v = ((const float4*)src)[i];
    __half2 h01 = __floats2half2_rn(v.x, v.y);
    __half2 h23 = __floats2half2_rn(v.z, v.w);
    float2 f01 = __half22float2(h01), f23 = __half22float2(h23);
    __half2 l01 = __floats2half2_rn(v.x - f01.x, v.y - f01.y);
    __half2 l23 = __floats2half2_rn(v.z - f23.x, v.w - f23.y);
    ((__half2*)hi)[2*i] = h01; ((__half2*)hi)[2*i+1] = h23;
    ((__half2*)lo)[2*i] = l01; ((__half2*)lo)[2*i+1] = l23;
}

#define W_Q4 (HH*HD*DD/4)
#define W_K4 (HHK*HD*DD/4)
#define W_O4 (DD*HH*HD/4)
__global__ void cast_all(const float* __restrict__ wq, const float* __restrict__ wk,
                         const float* __restrict__ wv, const float* __restrict__ wo,
                         __half* __restrict__ wqkv, __half* __restrict__ woh) {
    int i = blockIdx.x * blockDim.x + threadIdx.x;
    const float* src; __half* dst; int j;
    if (i < W_Q4)                { src = wq; dst = wqkv;                     j = i; }
    else if (i < W_Q4 + W_K4)    { src = wk; dst = wqkv + HH*HD*DD;          j = i - W_Q4; }
    else if (i < W_Q4 + 2*W_K4)  { src = wv; dst = wqkv + (HH+HHK)*HD*DD;    j = i - W_Q4 - W_K4; }
    else                         { src = wo; dst = woh;                      j = i - W_Q4 - 2*W_K4; }
    float4 v = ((const float4*)src)[j];
    ((__half2*)dst)[2*j]   = __floats2half2_rn(v.x, v.y);
    ((__half2*)dst)[2*j+1] = __floats2half2_rn(v.z, v.w);
}

__global__ void rope_table(float* __restrict__ ct, float* __restrict__ st) {
    int idx = blockIdx.x * blockDim.x + threadIdx.x;   // SS*64
    int s = idx >> 6, i = idx & 63;
    float inv_freq = powf(1.0e6f, -(float)i * (1.0f / 64.0f));
    float sn, cs;
    sincosf((float)s * inv_freq, &sn, &cs);
    ct[idx] = cs; st[idx] = sn;
}

// ============================================================
// HMMA fp16x2-split GEMM: C = A*W^T, A split hi/lo, W fp16.
// CTA 128x128, **BK=64**, 256 thr (8 warps, warp tile 64x32).
// 2-stage cp.async, stage 48KB (Ah 0, Al 16K, Bh 32K) = 96KB.
// Swizzle for 128B rows: atom ^= (row & 7).
// epi 0: fp32; epi 2: fused QKV segmented epilogue.
// ============================================================
#define GEMM_STAGE 49152
#define GEMM_SMEM  (2 * GEMM_STAGE)

__global__ __launch_bounds__(256)
void gemm_h(const __half* __restrict__ Ah, const __half* __restrict__ Al,
            const __half* __restrict__ Bh,
            float* __restrict__ Cf, float* __restrict__ Kf,
            __half* __restrict__ Ch, __half* __restrict__ Cl,
            int M, int N, int K, int epi) {
    extern __shared__ char smc[];
    const uint32_t sb = smem_u32(smc);
    const int tid  = threadIdx.x;
    const int lane = tid & 31;
    const int wid  = tid >> 5;          // 0..7
    const int wm   = wid & 1;           // 2 warps over M
    const int wn   = wid >> 1;          // 4 warps over N
    const int brow = blockIdx.y * 128;
    const int bcol = blockIdx.x * 128;

    const __half* Agh = Ah + (size_t)brow * K;
    const __half* Agl = Al + (size_t)brow * K;
    const __half* Bgh = Bh + (size_t)bcol * K;

    const int lr = tid >> 3;            // 0..31
    const int aq = tid & 7;             // atom 0..7 within 128B row

    auto issue = [&](int stage, int k0) {
        const uint32_t stb = sb + stage * GEMM_STAGE;
        #pragma unroll
        for (int i = 0; i < 4; ++i) {
            int r = lr + i * 32;
            uint32_t so = (uint32_t)(r * 128 + ((aq ^ (r & 7)) * 16));
            size_t go = (size_t)r * K + k0 + aq * 8;
            CP16(stb + so,         Agh + go);
            CP16(stb + 16384 + so, Agl + go);
            CP16(stb + 32768 + so, Bgh + go);
        }
    };

    float acc[4][4][4];
    #pragma unroll
    for (int mt = 0; mt < 4; ++mt)
        #pragma unroll
        for (int nt = 0; nt < 4; ++nt)
            #pragma unroll
            for (int e = 0; e < 4; ++e) acc[mt][nt][e] = 0.f;

    const int nk = K >> 6;              // chunks of 64
    issue(0, 0);  CP_COMMIT();
    issue(1, 64); CP_COMMIT();

    const int lrow16 = lane & 15;
    const int lhalf  = lane >> 4;

    for (int c = 0; c < nk; ++c) {
        CP_WAIT1();
        __syncthreads();
        const uint32_t stb = sb + (c & 1) * GEMM_STAGE;

        #pragma unroll
        for (int ks = 0; ks < 4; ++ks) {
            uint32_t ah[4][4], al[4][4], bh[2][4];
            #pragma unroll
            for (int mt = 0; mt < 4; ++mt) {
                int row = wm * 64 + mt * 16 + lrow16;
                int atom = (ks * 2 + lhalf) ^ (row & 7);
                uint32_t ad = stb + (uint32_t)(row * 128 + atom * 16);
                ldsm4(ah[mt], ad);
                ldsm4(al[mt], ad + 16384);
            }
            #pragma unroll
            for (int g2 = 0; g2 < 2; ++g2) {
                int row = wn * 32 + g2 * 16 + lrow16;
                int atom = (ks * 2 + lhalf) ^ (row & 7);
                uint32_t ad = stb + 32768 + (uint32_t)(row * 128 + atom * 16);
                ldsm4(bh[g2], ad);
            }
            #pragma unroll
            for (int mt = 0; mt < 4; ++mt)
                #pragma unroll
                for (int nt = 0; nt < 4; ++nt) {
                    const int g2 = nt >> 1, s2 = nt & 1;
                    mma16816(acc[mt][nt], ah[mt], bh[g2][s2], bh[g2][s2 + 2]);
                    mma16816(acc[mt][nt], al[mt], bh[g2][s2], bh[g2][s2 + 2]);
                }
        }
        __syncthreads();                     // all warps done reading stage c
        if (c + 2 < nk) issue(c & 1, (c + 2) << 6);
        CP_COMMIT();
    }

    // ---- epilogue ----
    #pragma unroll
    for (int mt = 0; mt < 4; ++mt) {
        int row = brow + wm * 64 + mt * 16 + (lane >> 2);
        #pragma unroll
        for (int nt = 0; nt < 4; ++nt) {
            int col = bcol + wn * 32 + nt * 8 + (lane & 3) * 2;
            if (epi == 0) {
                float* p0 = Cf + (size_t)row * N + col;
                *(float2*)p0 = make_float2(acc[mt][nt][0], acc[mt][nt][1]);
                *(float2*)(p0 + (size_t)8 * N) = make_float2(acc[mt][nt][2], acc[mt][nt][3]);
            } else {
                if (col < 2048) {
                    float* p0 = Cf + (size_t)row * 2048 + col;
                    *(float2*)p0 = make_float2(acc[mt][nt][0], acc[mt][nt][1]);
                    *(float2*)(p0 + (size_t)8 * 2048) = make_float2(acc[mt][nt][2], acc[mt][nt][3]);
                } else if (col < 3072) {
                    float* p0 = Kf + (size_t)row * 1024 + (col - 2048);
                    *(float2*)p0 = make_float2(acc[mt][nt][0], acc[mt][nt][1]);
                    *(float2*)(p0 + (size_t)8 * 1024) = make_float2(acc[mt][nt][2], acc[mt][nt][3]);
                } else {
                    size_t i0 = (size_t)row * 1024 + (col - 3072);
                    size_t i1 = i0 + (size_t)8 * 1024;
                    __half2 h01 = __floats2half2_rn(acc[mt][nt][0], acc[mt][nt][1]);
                    float2 f01 = __half22float2(h01);
                    __half2 l01 = __floats2half2_rn(acc[mt][nt][0] - f01.x,
                                                    acc[mt][nt][1] - f01.y);
                    __half2 h23 = __floats2half2_rn(acc[mt][nt][2], acc[mt][nt][3]);
                    float2 f23 = __half22float2(h23);
                    __half2 l23 = __floats2half2_rn(acc[mt][nt][2] - f23.x,
                                                    acc[mt][nt][3] - f23.y);
                    *(__half2*)(Ch + i0) = h01; *(__half2*)(Cl + i0) = l01;
                    *(__half2*)(Ch + i1) = h23; *(__half2*)(Cl + i1) = l23;
                }
            }
        }
    }
}

// ============================================================
// RMSNorm + RoPE (table-based), q and k in ONE launch.
// ============================================================
__global__ void norm_rope_all(const float* __restrict__ inq, const float* __restrict__ ink,
                              __half* __restrict__ qh, __half* __restrict__ ql,
                              __half* __restrict__ kh, __half* __restrict__ kl,
                              const float* __restrict__ qw, const float* __restrict__ kw,
                              const float* __restrict__ ct, const float* __restrict__ st) {
    const int tok = blockIdx.x;
    const int hy  = blockIdx.y;
    const int s   = tok & (SS - 1);
    const int d   = threadIdx.x;

    const bool isq = hy < HH;
    const int h       = isq ? hy : hy - HH;
    const int nheads  = isq ? HH : HHK;
    const float* in   = isq ? inq : ink;
    const float* w    = isq ? qw : kw;
    __half* oh        = isq ? qh : kh;
    __half* ol        = isq ? ql : kl;
    const float oscale = isq ? 0.08838834764831845f : 1.0f;

    const float* p = in + ((size_t)tok * nheads + h) * HD;
    float v = p[d];

    float ss = v * v;
    #pragma unroll
    for (int m = 16; m > 0; m >>= 1) ss += __shfl_xor_sync(0xffffffffu, ss, m);
    __shared__ float wsum[4];
    __shared__ float vals[HD];
    if ((d & 31) == 0) wsum[d >> 5] = ss;
    __syncthreads();
    float tot = wsum[0] + wsum[1] + wsum[2] + wsum[3];
    float r = rsqrtf(tot * (1.0f / 128.0f) + 1e-6f);
    float xn = v * r * w[d];
    vals[d] = xn;
    __syncthreads();

    int i = d & 63;
    float cs = ct[s * 64 + i];
    float sn = st[s * 64 + i];
    float o;
    if (d < 64) o = vals[d] * cs - vals[d + 64] * sn;
    else        o = vals[d] * cs + vals[d - 64] * sn;
    o *= oscale;

    __half hv = __float2half_rn(o);
    __half lv = __float2half_rn(o - __half2float(hv));
    size_t idx = ((size_t)tok * nheads + h) * HD + d;
    oh[idx] = hv;
    ol[idx] = lv;
}

// ============================================================
// Flash attention (R9): HMMA fp16-split, causal, GQA-fused,
// double-buffered K/V. smem 192KB.
// ============================================================
#define FLASH_SMEM 196608
#define SWF(r, a) ((uint32_t)((r) * 256 + ((((a) ^ (r)) & 7) | ((a) & 8)) * 16))

__global__ __launch_bounds__(256)
void flash_h(const __half* __restrict__ Qh, const __half* __restrict__ Ql,
             const __half* __restrict__ Kh, const __half* __restrict__ Kl,
             const __half* __restrict__ Vh, const __half* __restrict__ Vl,
             __half* __restrict__ Oh, __half* __restrict__ Ol) {
    extern __shared__ char smc[];
    const uint32_t sb = smem_u32(smc);
    const int qt = gridDim.x - 1 - blockIdx.x;
    const int kvh = blockIdx.y, b = blockIdx.z;
    const int tid = threadIdx.x, lane = tid & 31, wid = tid >> 5;
    const int g = lane >> 2, t4 = lane & 3;
    const int q0 = qt * 64;
    const int lr16 = lane & 15, lh = lane >> 4;
    const int wq4 = wid & 3;
    const int hsel = wid >> 2;
    const int h = 2 * kvh + hsel;

    const uint32_t QH = sb, QL = sb + 32768;
    const uint32_t KV0 = sb + 65536;

    {
        #pragma unroll
        for (int i = 0; i < 8; ++i) {
            int pos = tid + i * 256;
            int r = pos >> 4, a = pos & 15;
            int head = 2 * kvh + (r >> 6);
            int qrow = r & 63;
            uint32_t so = SWF(r, a);
            size_t go = (((size_t)(b * SS + q0 + qrow)) * HH + head) * HD + a * 8;
            CP16(QH + so, Qh + go);
            CP16(QL + so, Ql + go);
        }
        CP_COMMIT();
    }

    auto issue_kv = [&](int kt, int buf) {
        const uint32_t base = KV0 + buf * 65536;
        const int k0 = kt * 64;
        #pragma unroll
        for (int i = 0; i < 4; ++i) {
            int pos = tid + i * 256;
            int r = pos >> 4, a = pos & 15;
            uint32_t so = SWF(r, a);
            size_t go = (((size_t)(b * SS + k0 + r)) * HHK + kvh) * HD + a * 8;
            CP16(base + so,         Kh + go);
            CP16(base + 16384 + so, Kl + go);
            CP16(base + 32768 + so, Vh + go);
            CP16(base + 49152 + so, Vl + go);
        }
        CP_COMMIT();
    };

    issue_kv(0, 0);

    float oacc[16][4];
    #pragma unroll
    for (int nt = 0; nt < 16; ++nt)
        #pragma unroll
        for (int e = 0; e < 4; ++e) oacc[nt][e] = 0.f;
    float m0 = -INFINITY, m1 = -INFINITY, l0 = 0.f, l1 = 0.f;

    for (int kt = 0; kt <= qt; ++kt) {
        const int buf = kt & 1;
        const uint32_t KB = KV0 + buf * 65536;

        __syncthreads();
        if (kt < qt) { issue_kv(kt + 1, 1 - buf); CP_WAIT1(); }
        else         { CP_WAIT0(); }
        __syncthreads();

        float sacc[8][4];
        #pragma unroll
        for (int j = 0; j < 8; ++j)
            #pragma unroll
            for (int e = 0; e < 4; ++e) sacc[j][e] = 0.f;

        #pragma unroll
        for (int ks = 0; ks < 8; ++ks) {
            uint32_t qa[4], ql_[4];
            {
                int row = wid * 16 + lr16;
                int atom = 2 * ks + lh;
                uint32_t so = SWF(row, atom);
                ldsm4(qa, QH + so);
                ldsm4(ql_, QL + so);
            }
            uint32_t kf[4][4], kg[4][4];
            #pragma unroll
            for (int u = 0; u < 4; ++u) {
                int row = u * 16 + lr16;
                int atom = 2 * ks + lh;
                uint32_t so = SWF(row, atom);
                ldsm4(kf[u], KB + so);
                ldsm4(kg[u], KB + 16384 + so);
            }
            #pragma unroll
            for (int j = 0; j < 8; ++j) {
                const int u = j >> 1, s2 = j & 1;
                mma16816(sacc[j], qa,  kf[u][s2], kf[u][s2 + 2]);
                mma16816(sacc[j], qa,  kg[u][s2], kg[u][s2 + 2]);
                mma16816(sacc[j], ql_, kf[u][s2], kf[u][s2 + 2]);
            }
        }

        if (kt == qt) {
            #pragma unroll
            for (int j = 0; j < 8; ++j) {
                int colb = 8 * j + 2 * t4;
                int row0 = wq4 * 16 + g, row1 = row0 + 8;
                if (colb     > row0) sacc[j][0] = -1e30f;
                if (colb + 1 > row0) sacc[j][1] = -1e30f;
                if (colb     > row1) sacc[j][2] = -1e30f;
                if (colb + 1 > row1) sacc[j][3] = -1e30f;
            }
        }

        float mx0 = -INFINITY, mx1 = -INFINITY;
        #pragma unroll
        for (int j = 0; j < 8; ++j) {
            mx0 = fmaxf(mx0, fmaxf(sacc[j][0], sacc[j][1]));
            mx1 = fmaxf(mx1, fmaxf(sacc[j][2], sacc[j][3]));
        }
        mx0 = fmaxf(mx0, __shfl_xor_sync(0xffffffffu, mx0, 1));
        mx0 = fmaxf(mx0, __shfl_xor_sync(0xffffffffu, mx0, 2));
        mx1 = fmaxf(mx1, __shfl_xor_sync(0xffffffffu, mx1, 1));
        mx1 = fmaxf(mx1, __shfl_xor_sync(0xffffffffu, mx1, 2));
        float mn0 = fmaxf(m0, mx0), mn1 = fmaxf(m1, mx1);
        float al0 = __expf(m0 - mn0), al1 = __expf(m1 - mn1);
        m0 = mn0; m1 = mn1;

        float s0 = 0.f, s1 = 0.f;
        uint32_t pa[4][4];
        #pragma unroll
        for (int j = 0; j < 8; ++j) {
            float p0 = __expf(sacc[j][0] - mn0), p1 = __expf(sacc[j][1] - mn0);
            float p2 = __expf(sacc[j][2] - mn1), p3 = __expf(sacc[j][3] - mn1);
            __half2 hA = __floats2half2_rn(p0, p1);
            __half2 hB = __floats2half2_rn(p2, p3);
            float2 fA = __half22float2(hA), fB = __half22float2(hB);
            s0 += fA.x + fA.y;
            s1 += fB.x + fB.y;
            pa[j >> 1][(j & 1) * 2 + 0] = *(uint32_t*)&hA;
            pa[j >> 1][(j & 1) * 2 + 1] = *(uint32_t*)&hB;
        }
        s0 += __shfl_xor_sync(0xffffffffu, s0, 1);
        s0 += __shfl_xor_sync(0xffffffffu, s0, 2);
        s1 += __shfl_xor_sync(0xffffffffu, s1, 1);
        s1 += __shfl_xor_sync(0xffffffffu, s1, 2);
        l0 = l0 * al0 + s0;
        l1 = l1 * al1 + s1;
        #pragma unroll
        for (int nt = 0; nt < 16; ++nt) {
            oacc[nt][0] *= al0; oacc[nt][1] *= al0;
            oacc[nt][2] *= al1; oacc[nt][3] *= al1;
        }

        #pragma unroll
        for (int kc = 0; kc < 4; ++kc) {
            uint32_t vf[8][4];
            #pragma unroll
            for (int u = 0; u < 8; ++u) {
                int row = 16 * kc + lr16;
                int atom = 2 * u + lh;
                ldsm4t(vf[u], KB + 32768 + SWF(row, atom));
            }
            #pragma unroll
            for (int nt = 0; nt < 16; ++nt) {
                const int u = nt >> 1, s2 = (nt & 1) * 2;
                mma16816(oacc[nt], pa[kc], vf[u][s2], vf[u][s2 + 1]);
            }
            #pragma unroll
            for (int u = 0; u < 8; ++u) {
                int row = 16 * kc + lr16;
                int atom = 2 * u + lh;
                ldsm4t(vf[u], KB + 49152 + SWF(row, atom));
            }
            #pragma unroll
            for (int nt = 0; nt < 16; ++nt) {
                const int u = nt >> 1, s2 = (nt & 1) * 2;
                mma16816(oacc[nt], pa[kc], vf[u][s2], vf[u][s2 + 1]);
            }
        }
    }

    const float il0 = 1.0f / l0, il1 = 1.0f / l1;
    const int gr0 = q0 + wq4 * 16 + g;
    const int gr1 = gr0 + 8;
    #pragma unroll
    for (int nt = 0; nt < 16; ++nt) {
        float o0 = oacc[nt][0] * il0, o1 = oacc[nt][1] * il0;
        float o2 = oacc[nt][2] * il1, o3 = oacc[nt][3] * il1;
        int col = nt * 8 + t4 * 2;
        size_t i0 = ((size_t)(b * SS + gr0) * HH + h) * HD + col;
        size_t i1 = ((size_t)(b * SS + gr1) * HH + h) * HD + col;
        __half2 h01 = __floats2half2_rn(o0, o1);
        float2 f01 = __half22float2(h01);
        __half2 l01 = __floats2half2_rn(o0 - f01.x, o1 - f01.y);
        __half2 h23 = __floats2half2_rn(o2, o3);
        float2 f23 = __half22float2(h23);
        __half2 l23 = __floats2half2_rn(o2 - f23.x, o3 - f23.y);
        *(__half2*)(Oh + i0) = h01; *(__half2*)(Ol + i0) = l01;
        *(__half2*)(Oh + i1) = h23; *(__half2*)(Ol + i1) = l23;
    }
}

// ============================================================
// kernel_launch
// ============================================================
extern "C" void kernel_launch(void* const* d_in, const int* in_sizes, int n_in,
                              void* d_out, int out_size) {
    const float* x   = (const float*)d_in[0];
    const float* wq  = (const float*)d_in[1];
    const float* wk  = (const float*)d_in[2];
    const float* wv  = (const float*)d_in[3];
    const float* wo  = (const float*)d_in[4];
    const float* qnw = (const float*)d_in[5];
    const float* knw = (const float*)d_in[6];
    float* out = (float*)d_out;

    float *gq, *gk, *ct, *st;
    __half *xh, *xl, *wqkv, *woh;
    __half *qh, *ql, *kh, *kl, *vh, *vl, *ah, *al;
    cudaGetSymbolAddress((void**)&gq, g_q);
    cudaGetSymbolAddress((void**)&gk, g_k);
    cudaGetSymbolAddress((void**)&ct, g_ct);
    cudaGetSymbolAddress((void**)&st, g_st);
    cudaGetSymbolAddress((void**)&xh, g_xh);   cudaGetSymbolAddress((void**)&xl, g_xl);
    cudaGetSymbolAddress((void**)&wqkv, g_wqkv);
    cudaGetSymbolAddress((void**)&woh, g_woh);
    cudaGetSymbolAddress((void**)&qh, g_qh);   cudaGetSymbolAddress((void**)&ql, g_ql);
    cudaGetSymbolAddress((void**)&kh, g_kh);   cudaGetSymbolAddress((void**)&kl, g_kl);
    cudaGetSymbolAddress((void**)&vh, g_vh);   cudaGetSymbolAddress((void**)&vl, g_vl);
    cudaGetSymbolAddress((void**)&ah, g_ah);   cudaGetSymbolAddress((void**)&al, g_al);

    cudaFuncSetAttribute(gemm_h, cudaFuncAttributeMaxDynamicSharedMemorySize, GEMM_SMEM);
    cudaFuncSetAttribute(flash_h, cudaFuncAttributeMaxDynamicSharedMemorySize, FLASH_SMEM);

    // prep
    rope_table<<<(SS * 64) / 256, 256>>>(ct, st);
    split_fp16<<<(MM*DD/4 + 255)/256, 256>>>(x, xh, xl, MM*DD/4);
    cast_all<<<(W_Q4 + 2*W_K4 + W_O4) / 256, 256>>>(wq, wk, wv, wo, wqkv, woh);

    // fused QKV projection (N = 4096), segmented epilogue
    gemm_h<<<dim3(32, MM/128), 256, GEMM_SMEM>>>(
        xh, xl, wqkv, gq, gk, vh, vl, MM, 4096, DD, 2);

    // RMSNorm + RoPE (q and k fused into one launch)
    norm_rope_all<<<dim3(MM, HH + HHK), HD>>>(gq, gk, qh, ql, kh, kl,
                                              qnw, knw, ct, st);

    // causal flash attention
    flash_h<<<dim3(SS/64, HHK, BB), 256, FLASH_SMEM>>>(qh, ql, kh, kl, vh, vl, ah, al);

    // output projection
    gemm_h<<<dim3(DD/128, MM/128), 256, GEMM_SMEM>>>(
        ah, al, woh, out, nullptr, nullptr, nullptr, MM, DD, DD, 0);
}